// round 6
// baseline (speedup 1.0000x reference)
#include <cuda_runtime.h>
#include <math.h>

#define NN 50000
#define NE 600000
#define FEATS 128
#define WSTR 132
#define WSMEM (128 * WSTR * 4)

// -------------------- device scratch ---------------------------------------
__device__ __align__(128) unsigned g_gen;
__device__ __align__(128) unsigned g_cnt;
__device__ __align__(128) int g_idx64;
__device__ int g_count[NN];
__device__ int g_off[NN + 1];
__device__ int g_cursor[NN];
__device__ __align__(128) int g_btot[512];
__device__ int g_edges[NE];
__device__ float g_fx[NN * FEATS];   // feat @ W^T

// packed fp32x2 FMA (sm_103a; ptxas never auto-emits this)
#define FFMA2(d, a, b) \
    asm("fma.rn.f32x2 %0, %1, %2, %0;" : "+l"(d) : "l"(a), "l"(b))
#define PACKDUP(d, x) \
    asm("mov.b64 %0, {%1, %1};" : "=l"(d) : "r"(__float_as_uint(x)))

// -------------------- grid barrier (generation counter) ---------------------
__device__ __forceinline__ void gbar(unsigned& lg) {
    __syncthreads();
    if (threadIdx.x == 0) {
        __threadfence();
        unsigned arr = atomicAdd(&g_cnt, 1u);
        if (arr == gridDim.x - 1) {
            g_cnt = 0;
            __threadfence();
            *(volatile unsigned*)&g_gen = lg + 1;
        } else {
            while (*(volatile unsigned*)&g_gen == lg) { __nanosleep(64); }
        }
        __threadfence();
    }
    __syncthreads();
    lg++;
}

// ---------------------------------------------------------------------------
// CSR build: one persistent kernel, 4 grid barriers, no smem pressure.
// ---------------------------------------------------------------------------
__global__ __launch_bounds__(256, 2) void csr_build_kernel(
    const void* __restrict__ src, const void* __restrict__ dst, int nE) {
    __shared__ int wsum[9];
    __shared__ int Ssh[256];

    int tid = threadIdx.x;
    int lane = tid & 31;
    int warp = tid >> 5;
    int nth = gridDim.x * 256;
    int gt = blockIdx.x * 256 + tid;

    unsigned lg = *(volatile unsigned*)&g_gen;

    // ===== A: detect idx dtype + zero counts =====
    if (blockIdx.x == 0 && tid == 0) {
        const long long* p = (const long long*)src;
        int is64 = 1;
        for (int k = 0; k < 64; k++) {
            long long v = p[k];
            if (v < 0 || v >= NN) { is64 = 0; break; }
        }
        g_idx64 = is64;
    }
    for (int i = gt; i < NN; i += nth) g_count[i] = 0;
    gbar(lg);

    // ===== B: histogram of dst =====
    int idx64 = __ldcg(&g_idx64);
    if (idx64) {
        const long long* p = (const long long*)dst;
        for (int i = gt; i < nE; i += nth) atomicAdd(&g_count[(int)p[i]], 1);
    } else {
        const int* p = (const int*)dst;
        for (int i = gt; i < nE; i += nth) atomicAdd(&g_count[p[i]], 1);
    }
    gbar(lg);

    // ===== C: per-block-range exclusive scan with carry =====
    int per = ((NN + gridDim.x - 1) / gridDim.x + 255) & ~255;
    int rbeg = blockIdx.x * per;
    {
        int carry = 0;
        for (int base = rbeg; base < rbeg + per; base += 256) {
            int gid = base + tid;
            int v = (gid < NN) ? __ldcg(&g_count[gid]) : 0;
            int x = v;
            #pragma unroll
            for (int o = 1; o < 32; o <<= 1) {
                int y = __shfl_up_sync(0xffffffff, x, o);
                if (lane >= o) x += y;
            }
            if (lane == 31) wsum[warp] = x;
            __syncthreads();
            if (tid == 0) {
                int run = 0;
                #pragma unroll
                for (int i = 0; i < 8; i++) { int t = wsum[i]; wsum[i] = run; run += t; }
                wsum[8] = run;
            }
            __syncthreads();
            int excl = x - v + wsum[warp] + carry;
            if (gid < NN) g_off[gid] = excl;
            carry += wsum[8];
            __syncthreads();
        }
        if (tid == 0) g_btot[blockIdx.x] = carry;
    }
    gbar(lg);

    // ===== D: inter-block prefix, publish offsets + cursors =====
    {
        int pre = 0;
        for (int t = tid; t < (int)blockIdx.x; t += 256) pre += __ldcg(&g_btot[t]);
        Ssh[tid] = pre;
        __syncthreads();
        for (int o = 128; o > 0; o >>= 1) {
            if (tid < o) Ssh[tid] += Ssh[tid + o];
            __syncthreads();
        }
        int add = Ssh[0];
        for (int base = rbeg; base < rbeg + per; base += 256) {
            int gid = base + tid;
            if (gid < NN) {
                int o = g_off[gid] + add;
                g_off[gid] = o;
                g_cursor[gid] = o;
            }
        }
        if (blockIdx.x == 0 && tid == 0) g_off[NN] = nE;
    }
    gbar(lg);

    // ===== E: fill edge lists =====
    if (idx64) {
        const long long* ps = (const long long*)src;
        const long long* pd = (const long long*)dst;
        for (int i = gt; i < nE; i += nth) {
            int pos = atomicAdd(&g_cursor[(int)pd[i]], 1);
            g_edges[pos] = (int)ps[i];
        }
    } else {
        const int* ps = (const int*)src;
        const int* pd = (const int*)dst;
        for (int i = gt; i < nE; i += nth) {
            int pos = atomicAdd(&g_cursor[pd[i]], 1);
            g_edges[pos] = ps[i];
        }
    }
}

// ---------------------------------------------------------------------------
// Dense GEMM: g_fx = feat @ W^T. Persistent, occ 3/SM, FFMA2.
// Each warp: 8 rows; A-values read as uniform (broadcast) LDGs.
// ---------------------------------------------------------------------------
__global__ __launch_bounds__(256, 3) void gemm_kernel(
    const float* __restrict__ feat, const float* __restrict__ W, int nNodes) {
    extern __shared__ float Wsh[];   // [128][132], transposed
    int tid = threadIdx.x;
    int lane = tid & 31;
    int warp = tid >> 5;

    for (int idx = tid; idx < 128 * 128; idx += 256) {
        int j = idx >> 7;
        int k = idx & 127;
        Wsh[k * WSTR + j] = W[idx];
    }
    __syncthreads();

    int j0 = lane * 4;

    for (int tile = blockIdx.x * 64; tile < nNodes; tile += gridDim.x * 64) {
        int rbase = tile + warp * 8;
        int rows[8];
        #pragma unroll
        for (int r = 0; r < 8; r++) {
            int row = rbase + r;
            rows[r] = (row < nNodes) ? row : (nNodes - 1);
        }

        unsigned long long c[16];
        #pragma unroll
        for (int i = 0; i < 16; i++) c[i] = 0;

        #pragma unroll 1
        for (int k4 = 0; k4 < FEATS; k4 += 4) {
            float4 xv[8];
            #pragma unroll
            for (int r = 0; r < 8; r++)
                xv[r] = __ldg((const float4*)(feat + (long)rows[r] * FEATS + k4));
            #pragma unroll
            for (int kk = 0; kk < 4; kk++) {
                ulonglong2 wv =
                    *(const ulonglong2*)(Wsh + (k4 + kk) * WSTR + j0);
                #pragma unroll
                for (int r = 0; r < 8; r++) {
                    unsigned long long d;
                    PACKDUP(d, ((const float*)&xv[r])[kk]);
                    FFMA2(c[2 * r], wv.x, d);
                    FFMA2(c[2 * r + 1], wv.y, d);
                }
            }
        }

        #pragma unroll
        for (int r = 0; r < 8; r++) {
            int row = rbase + r;
            if (row < nNodes) {
                float2 lo = *(float2*)&c[2 * r];
                float2 hi = *(float2*)&c[2 * r + 1];
                *(float4*)(g_fx + (long)row * FEATS + j0) =
                    make_float4(lo.x, lo.y, hi.x, hi.y);
            }
        }
    }
}

// ---------------------------------------------------------------------------
// Gather + bias + tanh: out[n] = tanh(sum fx[srcs(n)] + b).
// Tiny smem -> high occupancy; warp per 4 nodes, predicated unroll-8.
// ---------------------------------------------------------------------------
__global__ __launch_bounds__(256) void gather_tanh_kernel(
    const float* __restrict__ b, float* __restrict__ out, int nNodes) {
    int gw = (blockIdx.x * blockDim.x + threadIdx.x) >> 5;
    int lane = threadIdx.x & 31;
    int l4 = lane * 4;
    float4 bv = *(const float4*)(b + l4);
    int nbase = gw * 4;
    if (nbase >= nNodes) return;

    #pragma unroll 1
    for (int r = 0; r < 4; r++) {
        int node = nbase + r;
        if (node >= nNodes) return;
        int eb = g_off[node];
        int ee = g_off[node + 1];
        float4 acc = make_float4(0.f, 0.f, 0.f, 0.f);
        for (int e = eb; e < ee; e += 8) {
            #pragma unroll
            for (int u = 0; u < 8; u++) {
                int j = e + u;
                int s = g_edges[j < ee ? j : eb];
                float4 f = *(const float4*)(g_fx + (long)s * FEATS + l4);
                if (j < ee) {
                    acc.x += f.x; acc.y += f.y;
                    acc.z += f.z; acc.w += f.w;
                }
            }
        }
        float4 o;
        o.x = tanhf(acc.x + bv.x);
        o.y = tanhf(acc.y + bv.y);
        o.z = tanhf(acc.z + bv.z);
        o.w = tanhf(acc.w + bv.w);
        *(float4*)(out + (long)node * FEATS + l4) = o;
    }
}

// ---------------------------------------------------------------------------
// Launcher: fork GEMM onto a second stream so it overlaps the CSR build;
// join before the gather. (Event-based fork/join is graph-capture legal.)
// ---------------------------------------------------------------------------
extern "C" void kernel_launch(void* const* d_in, const int* in_sizes, int n_in,
                              void* d_out, int out_size) {
    const float* feature = (const float*)d_in[0];
    const float* W       = (const float*)d_in[1];
    const float* b       = (const float*)d_in[2];
    const void*  src     = d_in[3];
    const void*  dst     = d_in[4];
    float* out = (float*)d_out;

    int nEdges = in_sizes[3];
    int nNodes = out_size / FEATS;

    static cudaStream_t s2 = nullptr;
    static cudaEvent_t eFork = nullptr, eJoin = nullptr;
    if (!s2) {
        cudaStreamCreateWithFlags(&s2, cudaStreamNonBlocking);
        cudaEventCreateWithFlags(&eFork, cudaEventDisableTiming);
        cudaEventCreateWithFlags(&eJoin, cudaEventDisableTiming);
        cudaFuncSetAttribute(gemm_kernel,
                             cudaFuncAttributeMaxDynamicSharedMemorySize, WSMEM);
    }

    // fork: GEMM on s2, CSR build on the main stream
    cudaEventRecord(eFork, 0);
    cudaStreamWaitEvent(s2, eFork, 0);
    gemm_kernel<<<444, 256, WSMEM, s2>>>(feature, W, nNodes);
    cudaEventRecord(eJoin, s2);

    csr_build_kernel<<<296, 256>>>(src, dst, nEdges);

    // join, then gather
    cudaStreamWaitEvent(0, eJoin, 0);
    gather_tanh_kernel<<<(nNodes + 31) / 32, 256>>>(b, out, nNodes);
}

// round 8
// speedup vs baseline: 1.4896x; 1.4896x over previous
#include <cuda_runtime.h>
#include <math.h>
#include <stdint.h>

#define NN 50000
#define NE 600000
#define FEATS 128
#define WSH_STRIDE 132
#define TILE_N 64
#define RPW 8
#define ESH_CAP 2048

#define SMEM_BYTES ((128 * WSH_STRIDE + TILE_N * FEATS) * 4 + ESH_CAP * 4 + 72 * 4)

#define CSR_BLOCKS 49
#define CSR_THREADS 1024

// -------------------- device scratch ---------------------------------------
__device__ __align__(128) unsigned g_gen;
__device__ __align__(128) unsigned g_cnt;
__device__ __align__(128) int g_idx64;
__device__ int g_count[NN];
__device__ int g_off[NN + 1];
__device__ int g_cursor[NN];
__device__ __align__(128) unsigned long long g_btot64[64];
__device__ int g_edges[NE];

// packed fp32x2 FMA (sm_103a; ptxas never auto-emits this)
#define FFMA2(d, a, b) \
    asm("fma.rn.f32x2 %0, %1, %2, %0;" : "+l"(d) : "l"(a), "l"(b))
#define PACKDUP(d, x) \
    asm("mov.b64 %0, {%1, %1};" : "=l"(d) : "r"(__float_as_uint(x)))

// -------------------- grid barrier (generation counter, proven in R5) -------
__device__ __forceinline__ void gbar(unsigned& lg) {
    __syncthreads();
    if (threadIdx.x == 0) {
        __threadfence();
        unsigned arr = atomicAdd(&g_cnt, 1u);
        if (arr == gridDim.x - 1) {
            g_cnt = 0;
            __threadfence();
            *(volatile unsigned*)&g_gen = lg + 1;
        } else {
            while (*(volatile unsigned*)&g_gen == lg) { __nanosleep(32); }
        }
        __threadfence();
    }
    __syncthreads();
    lg++;
}

// ---------------------------------------------------------------------------
// ONE-KERNEL CSR build: zero+detect | hist | scan(+decoupled lookback) | fill
// 49 blocks x 1024 threads; all blocks resident; 3 cheap grid barriers.
// ---------------------------------------------------------------------------
__global__ __launch_bounds__(CSR_THREADS, 1) void csr_all_kernel(
    const void* __restrict__ src, const void* __restrict__ dst, int nE) {
    __shared__ int wsum[32];
    __shared__ long long stot[64];

    int tid = threadIdx.x;
    int bid = blockIdx.x;
    int lane = tid & 31;
    int wid = tid >> 5;
    int nth = gridDim.x * CSR_THREADS;
    int gt = bid * CSR_THREADS + tid;

    unsigned lg = *(volatile unsigned*)&g_gen;
    unsigned tag = lg + 1;   // pass tag for lookback publications

    // ===== Phase 1: zero counts + detect idx dtype =====
    if (bid == 0 && tid == 0) {
        const long long* p = (const long long*)src;
        int is64 = 1;
        for (int k = 0; k < 64; k++) {
            long long v = p[k];
            if (v < 0 || v >= NN) { is64 = 0; break; }
        }
        g_idx64 = is64;
    }
    for (int i = gt; i < NN; i += nth) g_count[i] = 0;
    gbar(lg);

    // ===== Phase 2: histogram of dst =====
    int idx64 = __ldcg(&g_idx64);
    if (idx64) {
        const long long* p = (const long long*)dst;
        for (int i = gt; i < nE; i += nth) atomicAdd(&g_count[(int)p[i]], 1);
    } else {
        const int* p = (const int*)dst;
        for (int i = gt; i < nE; i += nth) atomicAdd(&g_count[p[i]], 1);
    }
    gbar(lg);

    // ===== Phase 3: chunk scan (block b scans elements [b*1024,(b+1)*1024)) ==
    {
        int gid = bid * CSR_THREADS + tid;
        int v = (gid < NN) ? __ldcg(&g_count[gid]) : 0;
        int x = v;
        #pragma unroll
        for (int o = 1; o < 32; o <<= 1) {
            int y = __shfl_up_sync(0xffffffff, x, o);
            if (lane >= o) x += y;
        }
        if (lane == 31) wsum[wid] = x;
        __syncthreads();
        if (wid == 0) {
            int s = wsum[lane];
            #pragma unroll
            for (int o = 1; o < 32; o <<= 1) {
                int y = __shfl_up_sync(0xffffffff, s, o);
                if (lane >= o) s += y;
            }
            wsum[lane] = s;
        }
        __syncthreads();
        int pre = (wid > 0) ? wsum[wid - 1] : 0;
        int incl = x + pre;
        int excl = incl - v;

        // publish my chunk total (pass-tagged), immediately
        if (tid == CSR_THREADS - 1) {
            unsigned long long val = ((unsigned long long)tag << 32) |
                                     (unsigned)incl;
            *(volatile unsigned long long*)&g_btot64[bid] = val;
            __threadfence();
        }

        // decoupled lookback: spin-read all predecessor totals in parallel
        if (tid < 64) {
            long long t = 0;
            if (tid < bid) {
                unsigned long long v64;
                do {
                    v64 = *(volatile unsigned long long*)&g_btot64[tid];
                } while ((unsigned)(v64 >> 32) != tag);
                t = (long long)(v64 & 0xffffffffULL);
            }
            stot[tid] = t;
        }
        __syncthreads();
        if (tid < 32) {
            long long s = stot[tid] + stot[tid + 32];
            #pragma unroll
            for (int o = 16; o > 0; o >>= 1)
                s += __shfl_down_sync(0xffffffff, s, o);
            if (tid == 0) stot[0] = s;
        }
        __syncthreads();
        int add = (int)stot[0];

        if (gid < NN) {
            int o = excl + add;
            g_off[gid] = o;
            g_cursor[gid] = o;
        }
        if (bid == 0 && tid == 0) g_off[NN] = nE;
    }
    gbar(lg);

    // ===== Phase 4: fill edge lists =====
    if (idx64) {
        const long long* ps = (const long long*)src;
        const long long* pd = (const long long*)dst;
        for (int i = gt; i < nE; i += nth) {
            int pos = atomicAdd(&g_cursor[(int)pd[i]], 1);
            g_edges[pos] = (int)ps[i];
        }
    } else {
        const int* ps = (const int*)src;
        const int* pd = (const int*)dst;
        for (int i = gt; i < nE; i += nth) {
            int pos = atomicAdd(&g_cursor[pd[i]], 1);
            g_edges[pos] = ps[i];
        }
    }
}

// ---------------------------------------------------------------------------
// Fused gather + GEMM + bias + tanh (verbatim from the 90.8us R4 kernel).
// ---------------------------------------------------------------------------
__global__ __launch_bounds__(256, 2) void gcn_fused_kernel(
    const float* __restrict__ feat, const float* __restrict__ W,
    const float* __restrict__ b, float* __restrict__ out, int nNodes) {
    extern __shared__ float sh[];
    float* Wsh = sh;                                  // [128][132]
    float* Ash = sh + 128 * WSH_STRIDE;               // [64][128]
    int*   Esh = (int*)(Ash + TILE_N * FEATS);        // [2048]
    int*   Osh = Esh + ESH_CAP;                       // [72]

    int tid = threadIdx.x;
    int lane = tid & 31;
    int warp = tid >> 5;
    int j0 = lane * 4;
    int lane4 = lane * 4;

    for (int idx = tid; idx < 128 * 128; idx += 256) {
        int j = idx >> 7;
        int k = idx & 127;
        Wsh[k * WSH_STRIDE + j] = W[idx];
    }

    float4 bias = *(const float4*)(b + j0);

    for (int tile = blockIdx.x * TILE_N; tile < nNodes; tile += gridDim.x * TILE_N) {
        __syncthreads();

        int tend = tile + TILE_N;
        if (tend > nNodes) tend = nNodes;
        int e0t = __ldg(&g_off[tile]);
        int e1t = __ldg(&g_off[tend]);
        int cnt = e1t - e0t;
        bool staged = (cnt <= ESH_CAP);
        if (tid <= TILE_N) {
            int nd = tile + tid;
            if (nd > nNodes) nd = nNodes;
            Osh[tid] = g_off[nd];
        }
        if (staged) {
            for (int i = tid; i < cnt; i += 256) Esh[i] = g_edges[e0t + i];
        }
        __syncthreads();

        float4 acc[RPW];
        #pragma unroll
        for (int r = 0; r < RPW; r++) acc[r] = make_float4(0.f, 0.f, 0.f, 0.f);

        #define GATHER_LOOP(IDXP)                                              \
            _Pragma("unroll")                                                  \
            for (int r = 0; r < RPW; r++) {                                    \
                int node = tile + warp * RPW + r;                              \
                if (node < nNodes) {                                           \
                    int eb = Osh[warp * RPW + r] - e0t;                        \
                    int ee = Osh[warp * RPW + r + 1] - e0t;                    \
                    for (int e = eb; e < ee; e += 8) {                         \
                        _Pragma("unroll")                                      \
                        for (int u = 0; u < 8; u++) {                          \
                            int j = e + u;                                     \
                            int s = (IDXP)[j < ee ? j : eb];                   \
                            float4 f = *(const float4*)(feat +                 \
                                          (long)s * FEATS + lane4);            \
                            if (j < ee) {                                      \
                                acc[r].x += f.x; acc[r].y += f.y;              \
                                acc[r].z += f.z; acc[r].w += f.w;              \
                            }                                                  \
                        }                                                      \
                    }                                                          \
                }                                                              \
            }

        if (staged) {
            GATHER_LOOP(Esh)
        } else {
            const int* gp = g_edges + e0t;
            GATHER_LOOP(gp)
        }
        #undef GATHER_LOOP

        #pragma unroll
        for (int r = 0; r < RPW; r++)
            *(float4*)(Ash + (warp * RPW + r) * FEATS + lane4) = acc[r];
        __syncthreads();

        const float* abase = Ash + warp * RPW * FEATS;
        unsigned long long c[2 * RPW];
        #pragma unroll
        for (int r = 0; r < 2 * RPW; r++) c[r] = 0;

        #pragma unroll 2
        for (int k4 = 0; k4 < FEATS; k4 += 4) {
            float4 xv[RPW];
            #pragma unroll
            for (int r = 0; r < RPW; r++)
                xv[r] = *(const float4*)(abase + r * FEATS + k4);
            #pragma unroll
            for (int kk = 0; kk < 4; kk++) {
                ulonglong2 wv =
                    *(const ulonglong2*)(Wsh + (k4 + kk) * WSH_STRIDE + j0);
                #pragma unroll
                for (int r = 0; r < RPW; r++) {
                    unsigned long long d;
                    PACKDUP(d, ((const float*)&xv[r])[kk]);
                    FFMA2(c[2 * r], wv.x, d);
                    FFMA2(c[2 * r + 1], wv.y, d);
                }
            }
        }

        int nbase = tile + warp * RPW;
        #pragma unroll
        for (int r = 0; r < RPW; r++) {
            if (nbase + r < nNodes) {
                float2 lo = *(float2*)&c[2 * r];
                float2 hi = *(float2*)&c[2 * r + 1];
                float4 o;
                o.x = tanhf(lo.x + bias.x);
                o.y = tanhf(lo.y + bias.y);
                o.z = tanhf(hi.x + bias.z);
                o.w = tanhf(hi.y + bias.w);
                *(float4*)(out + (long)(nbase + r) * FEATS + j0) = o;
            }
        }
    }
}

// ---------------------------------------------------------------------------
extern "C" void kernel_launch(void* const* d_in, const int* in_sizes, int n_in,
                              void* d_out, int out_size) {
    const float* feature = (const float*)d_in[0];
    const float* W       = (const float*)d_in[1];
    const float* b       = (const float*)d_in[2];
    const void*  src     = d_in[3];
    const void*  dst     = d_in[4];
    float* out = (float*)d_out;

    int nEdges = in_sizes[3];
    int nNodes = out_size / FEATS;

    csr_all_kernel<<<CSR_BLOCKS, CSR_THREADS>>>(src, dst, nEdges);

    cudaFuncSetAttribute(gcn_fused_kernel,
                         cudaFuncAttributeMaxDynamicSharedMemorySize, SMEM_BYTES);
    gcn_fused_kernel<<<296, 256, SMEM_BYTES>>>(feature, W, b, out, nNodes);
}

// round 9
// speedup vs baseline: 1.8294x; 1.2281x over previous
#include <cuda_runtime.h>
#include <math.h>
#include <stdint.h>

#define NN 50000
#define NE 600000
#define FEATS 128

#define CSR_BLOCKS 49
#define CSR_THREADS 1024

// -------------------- device scratch ---------------------------------------
__device__ __align__(128) unsigned g_gen;
__device__ __align__(128) unsigned g_cnt;
__device__ __align__(128) int g_idx64;
__device__ int g_count[NN];
__device__ int g_off[NN + 1];
__device__ int g_cursor[NN];
__device__ __align__(128) unsigned long long g_btot64[64];
__device__ int g_edges[NE];
__device__ float g_agg[NN * FEATS];

// -------------------- grid barrier ------------------------------------------
__device__ __forceinline__ void gbar(unsigned& lg) {
    __syncthreads();
    if (threadIdx.x == 0) {
        __threadfence();
        unsigned arr = atomicAdd(&g_cnt, 1u);
        if (arr == gridDim.x - 1) {
            g_cnt = 0;
            __threadfence();
            *(volatile unsigned*)&g_gen = lg + 1;
        } else {
            while (*(volatile unsigned*)&g_gen == lg) { __nanosleep(32); }
        }
        __threadfence();
    }
    __syncthreads();
    lg++;
}

// ---------------------------------------------------------------------------
// ONE-KERNEL CSR build (proven in R8).
// ---------------------------------------------------------------------------
__global__ __launch_bounds__(CSR_THREADS, 1) void csr_all_kernel(
    const void* __restrict__ src, const void* __restrict__ dst, int nE) {
    __shared__ int wsum[32];
    __shared__ long long stot[64];

    int tid = threadIdx.x;
    int bid = blockIdx.x;
    int lane = tid & 31;
    int wid = tid >> 5;
    int nth = gridDim.x * CSR_THREADS;
    int gt = bid * CSR_THREADS + tid;

    unsigned lg = *(volatile unsigned*)&g_gen;
    unsigned tag = lg + 1;

    if (bid == 0 && tid == 0) {
        const long long* p = (const long long*)src;
        int is64 = 1;
        for (int k = 0; k < 64; k++) {
            long long v = p[k];
            if (v < 0 || v >= NN) { is64 = 0; break; }
        }
        g_idx64 = is64;
    }
    for (int i = gt; i < NN; i += nth) g_count[i] = 0;
    gbar(lg);

    int idx64 = __ldcg(&g_idx64);
    if (idx64) {
        const long long* p = (const long long*)dst;
        for (int i = gt; i < nE; i += nth) atomicAdd(&g_count[(int)p[i]], 1);
    } else {
        const int* p = (const int*)dst;
        for (int i = gt; i < nE; i += nth) atomicAdd(&g_count[p[i]], 1);
    }
    gbar(lg);

    {
        int gid = bid * CSR_THREADS + tid;
        int v = (gid < NN) ? __ldcg(&g_count[gid]) : 0;
        int x = v;
        #pragma unroll
        for (int o = 1; o < 32; o <<= 1) {
            int y = __shfl_up_sync(0xffffffff, x, o);
            if (lane >= o) x += y;
        }
        if (lane == 31) wsum[wid] = x;
        __syncthreads();
        if (wid == 0) {
            int s = wsum[lane];
            #pragma unroll
            for (int o = 1; o < 32; o <<= 1) {
                int y = __shfl_up_sync(0xffffffff, s, o);
                if (lane >= o) s += y;
            }
            wsum[lane] = s;
        }
        __syncthreads();
        int pre = (wid > 0) ? wsum[wid - 1] : 0;
        int incl = x + pre;
        int excl = incl - v;

        if (tid == CSR_THREADS - 1) {
            unsigned long long val = ((unsigned long long)tag << 32) | (unsigned)incl;
            *(volatile unsigned long long*)&g_btot64[bid] = val;
            __threadfence();
        }
        if (tid < 64) {
            long long t = 0;
            if (tid < bid) {
                unsigned long long v64;
                do {
                    v64 = *(volatile unsigned long long*)&g_btot64[tid];
                } while ((unsigned)(v64 >> 32) != tag);
                t = (long long)(v64 & 0xffffffffULL);
            }
            stot[tid] = t;
        }
        __syncthreads();
        if (tid < 32) {
            long long s = stot[tid] + stot[tid + 32];
            #pragma unroll
            for (int o = 16; o > 0; o >>= 1)
                s += __shfl_down_sync(0xffffffff, s, o);
            if (tid == 0) stot[0] = s;
        }
        __syncthreads();
        int add = (int)stot[0];

        if (gid < NN) {
            int o = excl + add;
            g_off[gid] = o;
            g_cursor[gid] = o;
        }
        if (bid == 0 && tid == 0) g_off[NN] = nE;
    }
    gbar(lg);

    if (idx64) {
        const long long* ps = (const long long*)src;
        const long long* pd = (const long long*)dst;
        for (int i = gt; i < nE; i += nth) {
            int pos = atomicAdd(&g_cursor[(int)pd[i]], 1);
            g_edges[pos] = (int)ps[i];
        }
    } else {
        const int* ps = (const int*)src;
        const int* pd = (const int*)dst;
        for (int i = gt; i < nE; i += nth) {
            int pos = atomicAdd(&g_cursor[pd[i]], 1);
            g_edges[pos] = ps[i];
        }
    }
}

// ---------------------------------------------------------------------------
// Gather: agg[n] = sum feat[src]. One warp per node, zero smem, max occupancy.
// ---------------------------------------------------------------------------
__global__ __launch_bounds__(256) void gather_kernel(
    const float* __restrict__ feat, int nNodes) {
    int node = (blockIdx.x * 256 + threadIdx.x) >> 5;
    if (node >= nNodes) return;
    int l4 = (threadIdx.x & 31) * 4;
    int eb = __ldg(&g_off[node]);
    int ee = __ldg(&g_off[node + 1]);
    float4 acc = make_float4(0.f, 0.f, 0.f, 0.f);
    for (int e = eb; e < ee; e += 8) {
        #pragma unroll
        for (int u = 0; u < 8; u++) {
            int j = e + u;
            int s = g_edges[j < ee ? j : eb];
            float4 f = *(const float4*)(feat + (long)s * FEATS + l4);
            if (j < ee) {
                acc.x += f.x; acc.y += f.y;
                acc.z += f.z; acc.w += f.w;
            }
        }
    }
    *(float4*)(g_agg + (long)node * FEATS + l4) = acc;
}

// ---------------------------------------------------------------------------
// GEMM via mma.sync bf16 split: out = tanh(agg @ W^T + b).
// Tile: 64 nodes x 128 cols per block. smem stride 136 halves (conflict-free).
// ---------------------------------------------------------------------------
#define GSTR 136
#define SM_WH 0
#define SM_WL (SM_WH + 128 * GSTR * 2)
#define SM_AH (SM_WL + 128 * GSTR * 2)
#define SM_AL (SM_AH + 64 * GSTR * 2)
#define GEMM_SMEM (SM_AL + 64 * GSTR * 2)

#define MMA_BF16(c0, c1, c2, c3, a0, a1, a2, a3, b0, b1)                      \
    asm volatile(                                                             \
        "mma.sync.aligned.m16n8k16.row.col.f32.bf16.bf16.f32 "                \
        "{%0,%1,%2,%3}, {%4,%5,%6,%7}, {%8,%9}, {%0,%1,%2,%3};"               \
        : "+f"(c0), "+f"(c1), "+f"(c2), "+f"(c3)                              \
        : "r"(a0), "r"(a1), "r"(a2), "r"(a3), "r"(b0), "r"(b1))

__device__ __forceinline__ uint32_t pack_bf16(float lo, float hi) {
    uint32_t r;
    asm("cvt.rn.bf16x2.f32 %0, %1, %2;" : "=r"(r) : "f"(hi), "f"(lo));
    return r;
}

// convert float4 (4 consecutive k) -> hi pair + lo pair
__device__ __forceinline__ void split4(float4 a, uint2& h, uint2& l) {
    uint32_t h01 = pack_bf16(a.x, a.y);
    uint32_t h23 = pack_bf16(a.z, a.w);
    float r0 = a.x - __uint_as_float(h01 << 16);
    float r1 = a.y - __uint_as_float(h01 & 0xffff0000u);
    float r2 = a.z - __uint_as_float(h23 << 16);
    float r3 = a.w - __uint_as_float(h23 & 0xffff0000u);
    h = make_uint2(h01, h23);
    l = make_uint2(pack_bf16(r0, r1), pack_bf16(r2, r3));
}

__global__ __launch_bounds__(256, 2) void gemm_mma_kernel(
    const float* __restrict__ W, const float* __restrict__ b,
    float* __restrict__ out, int nNodes) {
    extern __shared__ char sm[];
    uint16_t* WH = (uint16_t*)(sm + SM_WH);
    uint16_t* WL = (uint16_t*)(sm + SM_WL);
    uint16_t* AH = (uint16_t*)(sm + SM_AH);
    uint16_t* AL = (uint16_t*)(sm + SM_AL);

    int tid = threadIdx.x;
    int lane = tid & 31;
    int warp = tid >> 5;
    int g = lane >> 2;        // 0..7
    int t = lane & 3;         // 0..3
    int mbase = (warp & 3) * 16;
    int nbase = (warp >> 2) * 64;

    // stage W (hi/lo) once per block
    for (int i = tid; i < 128 * 32; i += 256) {
        int j = i >> 5;
        int k4 = (i & 31) << 2;
        float4 w = __ldg((const float4*)(W + j * 128 + k4));
        uint2 h, l;
        split4(w, h, l);
        *(uint2*)(WH + j * GSTR + k4) = h;
        *(uint2*)(WL + j * GSTR + k4) = l;
    }

    // bias per lane: 8 n-chunks x 2 cols
    float2 bv[8];
    #pragma unroll
    for (int nc = 0; nc < 8; nc++)
        bv[nc] = *(const float2*)(b + nbase + nc * 8 + t * 2);

    for (int tile = blockIdx.x * 64; tile < nNodes; tile += gridDim.x * 64) {
        __syncthreads();   // A reuse (also orders W staging on iter 0)

        // stage A tile: 64 rows of agg -> bf16 hi/lo
        for (int i = tid; i < 64 * 32; i += 256) {
            int r = i >> 5;
            int k4 = (i & 31) << 2;
            int row = tile + r;
            if (row >= nNodes) row = nNodes - 1;
            float4 a = *(const float4*)(g_agg + (long)row * 128 + k4);
            uint2 h, l;
            split4(a, h, l);
            *(uint2*)(AH + r * GSTR + k4) = h;
            *(uint2*)(AL + r * GSTR + k4) = l;
        }
        __syncthreads();

        float c[8][4];
        #pragma unroll
        for (int nc = 0; nc < 8; nc++)
            #pragma unroll
            for (int i = 0; i < 4; i++) c[nc][i] = 0.f;

        #pragma unroll 1
        for (int kc = 0; kc < 8; kc++) {
            int k0 = kc * 16;
            // A fragments (hi & lo): rows mbase+g, mbase+g+8; k pairs t*2, t*2+8
            const uint16_t* arh = AH + (mbase + g) * GSTR + k0;
            const uint16_t* arl = AL + (mbase + g) * GSTR + k0;
            uint32_t ah0 = *(const uint32_t*)(arh + t * 2);
            uint32_t ah1 = *(const uint32_t*)(arh + 8 * GSTR + t * 2);
            uint32_t ah2 = *(const uint32_t*)(arh + t * 2 + 8);
            uint32_t ah3 = *(const uint32_t*)(arh + 8 * GSTR + t * 2 + 8);
            uint32_t al0 = *(const uint32_t*)(arl + t * 2);
            uint32_t al1 = *(const uint32_t*)(arl + 8 * GSTR + t * 2);
            uint32_t al2 = *(const uint32_t*)(arl + t * 2 + 8);
            uint32_t al3 = *(const uint32_t*)(arl + 8 * GSTR + t * 2 + 8);

            #pragma unroll
            for (int nc = 0; nc < 8; nc++) {
                int j = nbase + nc * 8 + g;
                uint32_t bh0 = *(const uint32_t*)(WH + j * GSTR + k0 + t * 2);
                uint32_t bh1 = *(const uint32_t*)(WH + j * GSTR + k0 + t * 2 + 8);
                uint32_t bl0 = *(const uint32_t*)(WL + j * GSTR + k0 + t * 2);
                uint32_t bl1 = *(const uint32_t*)(WL + j * GSTR + k0 + t * 2 + 8);
                MMA_BF16(c[nc][0], c[nc][1], c[nc][2], c[nc][3],
                         ah0, ah1, ah2, ah3, bh0, bh1);
                MMA_BF16(c[nc][0], c[nc][1], c[nc][2], c[nc][3],
                         ah0, ah1, ah2, ah3, bl0, bl1);
                MMA_BF16(c[nc][0], c[nc][1], c[nc][2], c[nc][3],
                         al0, al1, al2, al3, bh0, bh1);
            }
        }

        // epilogue: bias + tanh + store
        int row0 = tile + mbase + g;
        int row1 = row0 + 8;
        #pragma unroll
        for (int nc = 0; nc < 8; nc++) {
            int n0 = nbase + nc * 8 + t * 2;
            if (row0 < nNodes) {
                float2 o0;
                o0.x = tanhf(c[nc][0] + bv[nc].x);
                o0.y = tanhf(c[nc][1] + bv[nc].y);
                *(float2*)(out + (long)row0 * 128 + n0) = o0;
            }
            if (row1 < nNodes) {
                float2 o1;
                o1.x = tanhf(c[nc][2] + bv[nc].x);
                o1.y = tanhf(c[nc][3] + bv[nc].y);
                *(float2*)(out + (long)row1 * 128 + n0) = o1;
            }
        }
    }
}

// ---------------------------------------------------------------------------
extern "C" void kernel_launch(void* const* d_in, const int* in_sizes, int n_in,
                              void* d_out, int out_size) {
    const float* feature = (const float*)d_in[0];
    const float* W       = (const float*)d_in[1];
    const float* b       = (const float*)d_in[2];
    const void*  src     = d_in[3];
    const void*  dst     = d_in[4];
    float* out = (float*)d_out;

    int nEdges = in_sizes[3];
    int nNodes = out_size / FEATS;

    csr_all_kernel<<<CSR_BLOCKS, CSR_THREADS>>>(src, dst, nEdges);

    gather_kernel<<<(nNodes * 32 + 255) / 256, 256>>>(feature, nNodes);

    cudaFuncSetAttribute(gemm_mma_kernel,
                         cudaFuncAttributeMaxDynamicSharedMemorySize, GEMM_SMEM);
    gemm_mma_kernel<<<296, 256, GEMM_SMEM>>>(W, b, out, nNodes);
}

// round 10
// speedup vs baseline: 1.9869x; 1.0861x over previous
#include <cuda_runtime.h>
#include <math.h>
#include <stdint.h>

#define NN 50000
#define NE 600000
#define FEATS 128

#define CSR_BLOCKS 148
#define CSR_THREADS 1024
#define SCAN_CHUNK 1024
#define NCHUNK ((NN + SCAN_CHUNK - 1) / SCAN_CHUNK)   // 49

// -------------------- device scratch ---------------------------------------
__device__ __align__(128) unsigned g_gen;
__device__ __align__(128) unsigned g_cnt;
__device__ __align__(128) int g_idx64;
__device__ int g_count[NN];
__device__ int g_off[NN + 1];
__device__ int g_cursor[NN];
__device__ __align__(128) unsigned long long g_btot64[64];
__device__ int g_edges[NE];
__device__ float g_agg[NN * FEATS];

// -------------------- grid barrier ------------------------------------------
__device__ __forceinline__ void gbar(unsigned& lg) {
    __syncthreads();
    if (threadIdx.x == 0) {
        __threadfence();
        unsigned arr = atomicAdd(&g_cnt, 1u);
        if (arr == gridDim.x - 1) {
            g_cnt = 0;
            __threadfence();
            *(volatile unsigned*)&g_gen = lg + 1;
        } else {
            while (*(volatile unsigned*)&g_gen == lg) { __nanosleep(32); }
        }
        __threadfence();
    }
    __syncthreads();
    lg++;
}

// ---------------------------------------------------------------------------
// ONE-KERNEL CSR build, now on the FULL chip (148 blocks, 1/SM, all resident).
// Scan phase runs on blocks 0..48 (49 chunks of 1024); others skip to barrier.
// ---------------------------------------------------------------------------
__global__ __launch_bounds__(CSR_THREADS, 1) void csr_all_kernel(
    const void* __restrict__ src, const void* __restrict__ dst, int nE) {
    __shared__ int wsum[32];
    __shared__ long long stot[64];

    int tid = threadIdx.x;
    int bid = blockIdx.x;
    int lane = tid & 31;
    int wid = tid >> 5;
    int nth = gridDim.x * CSR_THREADS;
    int gt = bid * CSR_THREADS + tid;

    unsigned lg = *(volatile unsigned*)&g_gen;
    unsigned tag = lg + 1;

    // ===== Phase 1: zero counts + detect idx dtype =====
    if (bid == 0 && tid == 0) {
        const long long* p = (const long long*)src;
        int is64 = 1;
        for (int k = 0; k < 64; k++) {
            long long v = p[k];
            if (v < 0 || v >= NN) { is64 = 0; break; }
        }
        g_idx64 = is64;
    }
    for (int i = gt; i < NN; i += nth) g_count[i] = 0;
    gbar(lg);

    // ===== Phase 2: histogram of dst (full chip) =====
    int idx64 = __ldcg(&g_idx64);
    if (idx64) {
        const long long* p = (const long long*)dst;
        for (int i = gt; i < nE; i += nth) atomicAdd(&g_count[(int)p[i]], 1);
    } else {
        const int* p = (const int*)dst;
        for (int i = gt; i < nE; i += nth) atomicAdd(&g_count[p[i]], 1);
    }
    gbar(lg);

    // ===== Phase 3: chunk scan + decoupled lookback (blocks 0..NCHUNK-1) ====
    if (bid < NCHUNK) {
        int gid = bid * SCAN_CHUNK + tid;
        int v = (gid < NN) ? __ldcg(&g_count[gid]) : 0;
        int x = v;
        #pragma unroll
        for (int o = 1; o < 32; o <<= 1) {
            int y = __shfl_up_sync(0xffffffff, x, o);
            if (lane >= o) x += y;
        }
        if (lane == 31) wsum[wid] = x;
        __syncthreads();
        if (wid == 0) {
            int s = wsum[lane];
            #pragma unroll
            for (int o = 1; o < 32; o <<= 1) {
                int y = __shfl_up_sync(0xffffffff, s, o);
                if (lane >= o) s += y;
            }
            wsum[lane] = s;
        }
        __syncthreads();
        int pre = (wid > 0) ? wsum[wid - 1] : 0;
        int incl = x + pre;
        int excl = incl - v;

        if (tid == CSR_THREADS - 1) {
            unsigned long long val = ((unsigned long long)tag << 32) | (unsigned)incl;
            *(volatile unsigned long long*)&g_btot64[bid] = val;
            __threadfence();
        }
        if (tid < 64) {
            long long t = 0;
            if (tid < bid) {
                unsigned long long v64;
                do {
                    v64 = *(volatile unsigned long long*)&g_btot64[tid];
                } while ((unsigned)(v64 >> 32) != tag);
                t = (long long)(v64 & 0xffffffffULL);
            }
            stot[tid] = t;
        }
        __syncthreads();
        if (tid < 32) {
            long long s = stot[tid] + stot[tid + 32];
            #pragma unroll
            for (int o = 16; o > 0; o >>= 1)
                s += __shfl_down_sync(0xffffffff, s, o);
            if (tid == 0) stot[0] = s;
        }
        __syncthreads();
        int add = (int)stot[0];

        if (gid < NN) {
            int o = excl + add;
            g_off[gid] = o;
            g_cursor[gid] = o;
        }
        if (bid == 0 && tid == 0) g_off[NN] = nE;
    }
    gbar(lg);

    // ===== Phase 4: fill edge lists (full chip) =====
    if (idx64) {
        const long long* ps = (const long long*)src;
        const long long* pd = (const long long*)dst;
        for (int i = gt; i < nE; i += nth) {
            int pos = atomicAdd(&g_cursor[(int)pd[i]], 1);
            g_edges[pos] = (int)ps[i];
        }
    } else {
        const int* ps = (const int*)src;
        const int* pd = (const int*)dst;
        for (int i = gt; i < nE; i += nth) {
            int pos = atomicAdd(&g_cursor[pd[i]], 1);
            g_edges[pos] = ps[i];
        }
    }
}

// ---------------------------------------------------------------------------
// Gather: agg[n] = sum feat[src]. One warp per node, zero smem, max occupancy.
// ---------------------------------------------------------------------------
__global__ __launch_bounds__(256) void gather_kernel(
    const float* __restrict__ feat, int nNodes) {
    int node = (blockIdx.x * 256 + threadIdx.x) >> 5;
    if (node >= nNodes) return;
    int l4 = (threadIdx.x & 31) * 4;
    int eb = __ldg(&g_off[node]);
    int ee = __ldg(&g_off[node + 1]);
    float4 acc = make_float4(0.f, 0.f, 0.f, 0.f);
    for (int e = eb; e < ee; e += 8) {
        #pragma unroll
        for (int u = 0; u < 8; u++) {
            int j = e + u;
            int s = g_edges[j < ee ? j : eb];
            float4 f = *(const float4*)(feat + (long)s * FEATS + l4);
            if (j < ee) {
                acc.x += f.x; acc.y += f.y;
                acc.z += f.z; acc.w += f.w;
            }
        }
    }
    *(float4*)(g_agg + (long)node * FEATS + l4) = acc;
}

// ---------------------------------------------------------------------------
// GEMM via mma.sync bf16 split: out = tanh(agg @ W^T + b). (proven in R9)
// ---------------------------------------------------------------------------
#define GSTR 136
#define SM_WH 0
#define SM_WL (SM_WH + 128 * GSTR * 2)
#define SM_AH (SM_WL + 128 * GSTR * 2)
#define SM_AL (SM_AH + 64 * GSTR * 2)
#define GEMM_SMEM (SM_AL + 64 * GSTR * 2)

#define MMA_BF16(c0, c1, c2, c3, a0, a1, a2, a3, b0, b1)                      \
    asm volatile(                                                             \
        "mma.sync.aligned.m16n8k16.row.col.f32.bf16.bf16.f32 "                \
        "{%0,%1,%2,%3}, {%4,%5,%6,%7}, {%8,%9}, {%0,%1,%2,%3};"               \
        : "+f"(c0), "+f"(c1), "+f"(c2), "+f"(c3)                              \
        : "r"(a0), "r"(a1), "r"(a2), "r"(a3), "r"(b0), "r"(b1))

__device__ __forceinline__ uint32_t pack_bf16(float lo, float hi) {
    uint32_t r;
    asm("cvt.rn.bf16x2.f32 %0, %1, %2;" : "=r"(r) : "f"(hi), "f"(lo));
    return r;
}

__device__ __forceinline__ void split4(float4 a, uint2& h, uint2& l) {
    uint32_t h01 = pack_bf16(a.x, a.y);
    uint32_t h23 = pack_bf16(a.z, a.w);
    float r0 = a.x - __uint_as_float(h01 << 16);
    float r1 = a.y - __uint_as_float(h01 & 0xffff0000u);
    float r2 = a.z - __uint_as_float(h23 << 16);
    float r3 = a.w - __uint_as_float(h23 & 0xffff0000u);
    h = make_uint2(h01, h23);
    l = make_uint2(pack_bf16(r0, r1), pack_bf16(r2, r3));
}

__global__ __launch_bounds__(256, 2) void gemm_mma_kernel(
    const float* __restrict__ W, const float* __restrict__ b,
    float* __restrict__ out, int nNodes) {
    extern __shared__ char sm[];
    uint16_t* WH = (uint16_t*)(sm + SM_WH);
    uint16_t* WL = (uint16_t*)(sm + SM_WL);
    uint16_t* AH = (uint16_t*)(sm + SM_AH);
    uint16_t* AL = (uint16_t*)(sm + SM_AL);

    int tid = threadIdx.x;
    int lane = tid & 31;
    int warp = tid >> 5;
    int g = lane >> 2;
    int t = lane & 3;
    int mbase = (warp & 3) * 16;
    int nbase = (warp >> 2) * 64;

    for (int i = tid; i < 128 * 32; i += 256) {
        int j = i >> 5;
        int k4 = (i & 31) << 2;
        float4 w = __ldg((const float4*)(W + j * 128 + k4));
        uint2 h, l;
        split4(w, h, l);
        *(uint2*)(WH + j * GSTR + k4) = h;
        *(uint2*)(WL + j * GSTR + k4) = l;
    }

    float2 bv[8];
    #pragma unroll
    for (int nc = 0; nc < 8; nc++)
        bv[nc] = *(const float2*)(b + nbase + nc * 8 + t * 2);

    for (int tile = blockIdx.x * 64; tile < nNodes; tile += gridDim.x * 64) {
        __syncthreads();

        for (int i = tid; i < 64 * 32; i += 256) {
            int r = i >> 5;
            int k4 = (i & 31) << 2;
            int row = tile + r;
            if (row >= nNodes) row = nNodes - 1;
            float4 a = *(const float4*)(g_agg + (long)row * 128 + k4);
            uint2 h, l;
            split4(a, h, l);
            *(uint2*)(AH + r * GSTR + k4) = h;
            *(uint2*)(AL + r * GSTR + k4) = l;
        }
        __syncthreads();

        float c[8][4];
        #pragma unroll
        for (int nc = 0; nc < 8; nc++)
            #pragma unroll
            for (int i = 0; i < 4; i++) c[nc][i] = 0.f;

        #pragma unroll 1
        for (int kc = 0; kc < 8; kc++) {
            int k0 = kc * 16;
            const uint16_t* arh = AH + (mbase + g) * GSTR + k0;
            const uint16_t* arl = AL + (mbase + g) * GSTR + k0;
            uint32_t ah0 = *(const uint32_t*)(arh + t * 2);
            uint32_t ah1 = *(const uint32_t*)(arh + 8 * GSTR + t * 2);
            uint32_t ah2 = *(const uint32_t*)(arh + t * 2 + 8);
            uint32_t ah3 = *(const uint32_t*)(arh + 8 * GSTR + t * 2 + 8);
            uint32_t al0 = *(const uint32_t*)(arl + t * 2);
            uint32_t al1 = *(const uint32_t*)(arl + 8 * GSTR + t * 2);
            uint32_t al2 = *(const uint32_t*)(arl + t * 2 + 8);
            uint32_t al3 = *(const uint32_t*)(arl + 8 * GSTR + t * 2 + 8);

            #pragma unroll
            for (int nc = 0; nc < 8; nc++) {
                int j = nbase + nc * 8 + g;
                uint32_t bh0 = *(const uint32_t*)(WH + j * GSTR + k0 + t * 2);
                uint32_t bh1 = *(const uint32_t*)(WH + j * GSTR + k0 + t * 2 + 8);
                uint32_t bl0 = *(const uint32_t*)(WL + j * GSTR + k0 + t * 2);
                uint32_t bl1 = *(const uint32_t*)(WL + j * GSTR + k0 + t * 2 + 8);
                MMA_BF16(c[nc][0], c[nc][1], c[nc][2], c[nc][3],
                         ah0, ah1, ah2, ah3, bh0, bh1);
                MMA_BF16(c[nc][0], c[nc][1], c[nc][2], c[nc][3],
                         ah0, ah1, ah2, ah3, bl0, bl1);
                MMA_BF16(c[nc][0], c[nc][1], c[nc][2], c[nc][3],
                         al0, al1, al2, al3, bh0, bh1);
            }
        }

        int row0 = tile + mbase + g;
        int row1 = row0 + 8;
        #pragma unroll
        for (int nc = 0; nc < 8; nc++) {
            int n0 = nbase + nc * 8 + t * 2;
            if (row0 < nNodes) {
                float2 o0;
                o0.x = tanhf(c[nc][0] + bv[nc].x);
                o0.y = tanhf(c[nc][1] + bv[nc].y);
                *(float2*)(out + (long)row0 * 128 + n0) = o0;
            }
            if (row1 < nNodes) {
                float2 o1;
                o1.x = tanhf(c[nc][2] + bv[nc].x);
                o1.y = tanhf(c[nc][3] + bv[nc].y);
                *(float2*)(out + (long)row1 * 128 + n0) = o1;
            }
        }
    }
}

// ---------------------------------------------------------------------------
extern "C" void kernel_launch(void* const* d_in, const int* in_sizes, int n_in,
                              void* d_out, int out_size) {
    const float* feature = (const float*)d_in[0];
    const float* W       = (const float*)d_in[1];
    const float* b       = (const float*)d_in[2];
    const void*  src     = d_in[3];
    const void*  dst     = d_in[4];
    float* out = (float*)d_out;

    int nEdges = in_sizes[3];
    int nNodes = out_size / FEATS;

    csr_all_kernel<<<CSR_BLOCKS, CSR_THREADS>>>(src, dst, nEdges);

    gather_kernel<<<(nNodes * 32 + 255) / 256, 256>>>(feature, nNodes);

    cudaFuncSetAttribute(gemm_mma_kernel,
                         cudaFuncAttributeMaxDynamicSharedMemorySize, GEMM_SMEM);
    gemm_mma_kernel<<<296, 256, GEMM_SMEM>>>(W, b, out, nNodes);
}

// round 11
// speedup vs baseline: 2.0663x; 1.0399x over previous
#include <cuda_runtime.h>
#include <math.h>
#include <stdint.h>

#define NN 50000
#define NE 600000
#define FEATS 128

#define SCAN_CHUNK 1024
#define NCHUNK ((NN + SCAN_CHUNK - 1) / SCAN_CHUNK)   // 49

// -------------------- device scratch ---------------------------------------
__device__ __align__(128) int g_idx64;
__device__ int g_count[NN];
__device__ int g_off[NN + 1];
__device__ int g_cursor[NN];
__device__ __align__(128) int g_btot[64];
__device__ int g_edges[NE];
__device__ float g_agg[NN * FEATS];

__device__ __forceinline__ int load_idx(const void* p, int i) {
    return g_idx64 ? (int)((const long long*)p)[i] : ((const int*)p)[i];
}

// ======================= CSR build: 5 small kernels (proven ~14us in R4) ====
__global__ void init_kernel(const void* __restrict__ src) {
    int i = blockIdx.x * blockDim.x + threadIdx.x;
    if (i < NN) g_count[i] = 0;
    if (blockIdx.x == 0 && threadIdx.x == 0) {
        const long long* p = (const long long*)src;
        int is64 = 1;
        for (int k = 0; k < 64; k++) {
            long long v = p[k];
            if (v < 0 || v >= NN) { is64 = 0; break; }
        }
        g_idx64 = is64;
    }
}

__global__ void hist_kernel(const void* __restrict__ dst, int nE) {
    int i = (blockIdx.x * blockDim.x + threadIdx.x) * 2;
    if (g_idx64) {
        const long long* p = (const long long*)dst;
        if (i + 1 < nE) {
            longlong2 v = *(const longlong2*)(p + i);
            atomicAdd(&g_count[(int)v.x], 1);
            atomicAdd(&g_count[(int)v.y], 1);
        } else if (i < nE) {
            atomicAdd(&g_count[(int)p[i]], 1);
        }
    } else {
        const int* p = (const int*)dst;
        if (i + 1 < nE) {
            int2 v = *(const int2*)(p + i);
            atomicAdd(&g_count[v.x], 1);
            atomicAdd(&g_count[v.y], 1);
        } else if (i < nE) {
            atomicAdd(&g_count[p[i]], 1);
        }
    }
}

__global__ void scanA_kernel() {
    __shared__ int wsum[32];
    int t = threadIdx.x;
    int lane = t & 31, wid = t >> 5;
    int gid = blockIdx.x * SCAN_CHUNK + t;
    int v = (gid < NN) ? g_count[gid] : 0;
    int x = v;
    #pragma unroll
    for (int o = 1; o < 32; o <<= 1) {
        int y = __shfl_up_sync(0xffffffff, x, o);
        if (lane >= o) x += y;
    }
    if (lane == 31) wsum[wid] = x;
    __syncthreads();
    if (wid == 0) {
        int s = wsum[lane];
        #pragma unroll
        for (int o = 1; o < 32; o <<= 1) {
            int y = __shfl_up_sync(0xffffffff, s, o);
            if (lane >= o) s += y;
        }
        wsum[lane] = s;
    }
    __syncthreads();
    int pre = (wid > 0) ? wsum[wid - 1] : 0;
    int incl = x + pre;
    if (gid < NN) g_off[gid] = incl - v;
    if (t == SCAN_CHUNK - 1) g_btot[blockIdx.x] = incl;
}

__global__ void scanC_kernel(int nE) {
    __shared__ int sh[64];
    int t = threadIdx.x;
    if (t < 64) sh[t] = (t < NCHUNK && t < (int)blockIdx.x) ? g_btot[t] : 0;
    __syncthreads();
    for (int o = 32; o > 0; o >>= 1) {
        if (t < o) sh[t] += sh[t + o];
        __syncthreads();
    }
    int add = sh[0];
    int gid = blockIdx.x * SCAN_CHUNK + t;
    if (gid < NN) {
        int o = g_off[gid] + add;
        g_off[gid] = o;
        g_cursor[gid] = o;
    }
    if (blockIdx.x == 0 && t == 0) g_off[NN] = nE;
}

__global__ void fill_kernel(const void* __restrict__ src,
                            const void* __restrict__ dst, int nE) {
    int i = (blockIdx.x * blockDim.x + threadIdx.x) * 2;
    #pragma unroll
    for (int u = 0; u < 2; u++) {
        int j = i + u;
        if (j < nE) {
            int d = load_idx(dst, j);
            int s = load_idx(src, j);
            int pos = atomicAdd(&g_cursor[d], 1);
            g_edges[pos] = s;
        }
    }
}

// ======================= gather: agg[n] = sum feat[src] =====================
__global__ __launch_bounds__(256) void gather_kernel(
    const float* __restrict__ feat, int nNodes) {
    int node = (blockIdx.x * 256 + threadIdx.x) >> 5;
    if (node >= nNodes) return;
    int l4 = (threadIdx.x & 31) * 4;
    int eb = __ldg(&g_off[node]);
    int ee = __ldg(&g_off[node + 1]);
    float4 acc = make_float4(0.f, 0.f, 0.f, 0.f);
    for (int e = eb; e < ee; e += 8) {
        #pragma unroll
        for (int u = 0; u < 8; u++) {
            int j = e + u;
            int s = g_edges[j < ee ? j : eb];
            float4 f = *(const float4*)(feat + (long)s * FEATS + l4);
            if (j < ee) {
                acc.x += f.x; acc.y += f.y;
                acc.z += f.z; acc.w += f.w;
            }
        }
    }
    *(float4*)(g_agg + (long)node * FEATS + l4) = acc;
}

// ======================= GEMM via mma.sync bf16 split (proven R9/R10) =======
#define GSTR 136
#define SM_WH 0
#define SM_WL (SM_WH + 128 * GSTR * 2)
#define SM_AH (SM_WL + 128 * GSTR * 2)
#define SM_AL (SM_AH + 64 * GSTR * 2)
#define GEMM_SMEM (SM_AL + 64 * GSTR * 2)

#define MMA_BF16(c0, c1, c2, c3, a0, a1, a2, a3, b0, b1)                      \
    asm volatile(                                                             \
        "mma.sync.aligned.m16n8k16.row.col.f32.bf16.bf16.f32 "                \
        "{%0,%1,%2,%3}, {%4,%5,%6,%7}, {%8,%9}, {%0,%1,%2,%3};"               \
        : "+f"(c0), "+f"(c1), "+f"(c2), "+f"(c3)                              \
        : "r"(a0), "r"(a1), "r"(a2), "r"(a3), "r"(b0), "r"(b1))

__device__ __forceinline__ uint32_t pack_bf16(float lo, float hi) {
    uint32_t r;
    asm("cvt.rn.bf16x2.f32 %0, %1, %2;" : "=r"(r) : "f"(hi), "f"(lo));
    return r;
}

__device__ __forceinline__ void split4(float4 a, uint2& h, uint2& l) {
    uint32_t h01 = pack_bf16(a.x, a.y);
    uint32_t h23 = pack_bf16(a.z, a.w);
    float r0 = a.x - __uint_as_float(h01 << 16);
    float r1 = a.y - __uint_as_float(h01 & 0xffff0000u);
    float r2 = a.z - __uint_as_float(h23 << 16);
    float r3 = a.w - __uint_as_float(h23 & 0xffff0000u);
    h = make_uint2(h01, h23);
    l = make_uint2(pack_bf16(r0, r1), pack_bf16(r2, r3));
}

__global__ __launch_bounds__(256, 2) void gemm_mma_kernel(
    const float* __restrict__ W, const float* __restrict__ b,
    float* __restrict__ out, int nNodes) {
    extern __shared__ char sm[];
    uint16_t* WH = (uint16_t*)(sm + SM_WH);
    uint16_t* WL = (uint16_t*)(sm + SM_WL);
    uint16_t* AH = (uint16_t*)(sm + SM_AH);
    uint16_t* AL = (uint16_t*)(sm + SM_AL);

    int tid = threadIdx.x;
    int lane = tid & 31;
    int warp = tid >> 5;
    int g = lane >> 2;
    int t = lane & 3;
    int mbase = (warp & 3) * 16;
    int nbase = (warp >> 2) * 64;

    for (int i = tid; i < 128 * 32; i += 256) {
        int j = i >> 5;
        int k4 = (i & 31) << 2;
        float4 w = __ldg((const float4*)(W + j * 128 + k4));
        uint2 h, l;
        split4(w, h, l);
        *(uint2*)(WH + j * GSTR + k4) = h;
        *(uint2*)(WL + j * GSTR + k4) = l;
    }

    float2 bv[8];
    #pragma unroll
    for (int nc = 0; nc < 8; nc++)
        bv[nc] = *(const float2*)(b + nbase + nc * 8 + t * 2);

    for (int tile = blockIdx.x * 64; tile < nNodes; tile += gridDim.x * 64) {
        __syncthreads();

        for (int i = tid; i < 64 * 32; i += 256) {
            int r = i >> 5;
            int k4 = (i & 31) << 2;
            int row = tile + r;
            if (row >= nNodes) row = nNodes - 1;
            float4 a = *(const float4*)(g_agg + (long)row * 128 + k4);
            uint2 h, l;
            split4(a, h, l);
            *(uint2*)(AH + r * GSTR + k4) = h;
            *(uint2*)(AL + r * GSTR + k4) = l;
        }
        __syncthreads();

        float c[8][4];
        #pragma unroll
        for (int nc = 0; nc < 8; nc++)
            #pragma unroll
            for (int i = 0; i < 4; i++) c[nc][i] = 0.f;

        #pragma unroll 1
        for (int kc = 0; kc < 8; kc++) {
            int k0 = kc * 16;
            const uint16_t* arh = AH + (mbase + g) * GSTR + k0;
            const uint16_t* arl = AL + (mbase + g) * GSTR + k0;
            uint32_t ah0 = *(const uint32_t*)(arh + t * 2);
            uint32_t ah1 = *(const uint32_t*)(arh + 8 * GSTR + t * 2);
            uint32_t ah2 = *(const uint32_t*)(arh + t * 2 + 8);
            uint32_t ah3 = *(const uint32_t*)(arh + 8 * GSTR + t * 2 + 8);
            uint32_t al0 = *(const uint32_t*)(arl + t * 2);
            uint32_t al1 = *(const uint32_t*)(arl + 8 * GSTR + t * 2);
            uint32_t al2 = *(const uint32_t*)(arl + t * 2 + 8);
            uint32_t al3 = *(const uint32_t*)(arl + 8 * GSTR + t * 2 + 8);

            #pragma unroll
            for (int nc = 0; nc < 8; nc++) {
                int j = nbase + nc * 8 + g;
                uint32_t bh0 = *(const uint32_t*)(WH + j * GSTR + k0 + t * 2);
                uint32_t bh1 = *(const uint32_t*)(WH + j * GSTR + k0 + t * 2 + 8);
                uint32_t bl0 = *(const uint32_t*)(WL + j * GSTR + k0 + t * 2);
                uint32_t bl1 = *(const uint32_t*)(WL + j * GSTR + k0 + t * 2 + 8);
                MMA_BF16(c[nc][0], c[nc][1], c[nc][2], c[nc][3],
                         ah0, ah1, ah2, ah3, bh0, bh1);
                MMA_BF16(c[nc][0], c[nc][1], c[nc][2], c[nc][3],
                         ah0, ah1, ah2, ah3, bl0, bl1);
                MMA_BF16(c[nc][0], c[nc][1], c[nc][2], c[nc][3],
                         al0, al1, al2, al3, bh0, bh1);
            }
        }

        int row0 = tile + mbase + g;
        int row1 = row0 + 8;
        #pragma unroll
        for (int nc = 0; nc < 8; nc++) {
            int n0 = nbase + nc * 8 + t * 2;
            if (row0 < nNodes) {
                float2 o0;
                o0.x = tanhf(c[nc][0] + bv[nc].x);
                o0.y = tanhf(c[nc][1] + bv[nc].y);
                *(float2*)(out + (long)row0 * 128 + n0) = o0;
            }
            if (row1 < nNodes) {
                float2 o1;
                o1.x = tanhf(c[nc][2] + bv[nc].x);
                o1.y = tanhf(c[nc][3] + bv[nc].y);
                *(float2*)(out + (long)row1 * 128 + n0) = o1;
            }
        }
    }
}

// ---------------------------------------------------------------------------
extern "C" void kernel_launch(void* const* d_in, const int* in_sizes, int n_in,
                              void* d_out, int out_size) {
    const float* feature = (const float*)d_in[0];
    const float* W       = (const float*)d_in[1];
    const float* b       = (const float*)d_in[2];
    const void*  src     = d_in[3];
    const void*  dst     = d_in[4];
    float* out = (float*)d_out;

    int nEdges = in_sizes[3];
    int nNodes = out_size / FEATS;

    // CSR build: 5 small kernels (fast under graph replay)
    init_kernel<<<(NN + 511) / 512, 512>>>(src);
    hist_kernel<<<(nEdges / 2 + 511) / 512, 512>>>(dst, nEdges);
    scanA_kernel<<<NCHUNK, SCAN_CHUNK>>>();
    scanC_kernel<<<NCHUNK, SCAN_CHUNK>>>(nEdges);
    fill_kernel<<<(nEdges / 2 + 511) / 512, 512>>>(src, dst, nEdges);

    gather_kernel<<<(nNodes * 32 + 255) / 256, 256>>>(feature, nNodes);

    cudaFuncSetAttribute(gemm_mma_kernel,
                         cudaFuncAttributeMaxDynamicSharedMemorySize, GEMM_SMEM);
    gemm_mma_kernel<<<296, 256, GEMM_SMEM>>>(W, b, out, nNodes);
}